// round 11
// baseline (speedup 1.0000x reference)
#include <cuda_runtime.h>
#include <cuda_bf16.h>
#include <cuda_fp16.h>
#include <math.h>

// ---------------------------------------------------------------------------
// SCM: out = PWL( eps @ inv(I - A) )
//   eps: [B,16] f32, A: [16,16] f32, p: [16,101] f32, b: [16] f32
// Table per (dim, idx): half2{w, c}, c = delta_bias[spi] - sp*w -> out=fma(z,w,c)
// GEMV: packed fp32x2 FMA (FFMA2) vs 64-bit constant words.
// Main kernel processes TWO rows per thread per iteration: the 128 LDCU.64
// constant reads are shared by both rows, and per-thread MLP doubles.
// ---------------------------------------------------------------------------

#define NP1 101
#define DIMS 16
#define VMIN_F (-5.0f)
#define INT_LEN_F (10.0f / 99.0f)
#define INV_INT_LEN_F (99.0f / 10.0f)

__device__ float    g_M[DIMS * DIMS];
__device__ __half2  g_tab[DIMS * NP1];
__constant__ unsigned long long c_M2[DIMS * 8];

__device__ __forceinline__ unsigned long long ffma2(unsigned long long a,
                                                    unsigned long long b,
                                                    unsigned long long c) {
    unsigned long long d;
    asm("fma.rn.f32x2 %0, %1, %2, %3;" : "=l"(d) : "l"(a), "l"(b), "l"(c));
    return d;
}
__device__ __forceinline__ unsigned long long pack2(float x) {
    unsigned long long d;
    asm("mov.b64 %0, {%1, %1};" : "=l"(d) : "f"(x));
    return d;
}
__device__ __forceinline__ void unpack2(unsigned long long v, float& lo, float& hi) {
    asm("mov.b64 {%0, %1}, %2;" : "=f"(lo), "=f"(hi) : "l"(v));
}

// ---------------------------------------------------------------------------
// Prep: 1 block, 544 threads (17 warps), NO barriers.
//   warp 16: 16x16 Gauss-Jordan inverse, rows in registers, shuffle-only.
//   warps 0..15: PWL table for dim = warp id, register-only with lane halos.
// ---------------------------------------------------------------------------
__global__ void __launch_bounds__(544) prep_kernel(const float* __restrict__ A,
                                                   const float* __restrict__ p,
                                                   const float* __restrict__ b) {
    const int warp = threadIdx.x >> 5;
    const int lane = threadIdx.x & 31;
    const unsigned FULL = 0xffffffffu;

    if (warp == 16) {
        float a[32];
        const int r = lane;
#pragma unroll
        for (int c = 0; c < 16; ++c) {
            float Av = (r < 16) ? A[r * 16 + c] : 0.0f;
            a[c]      = (r == c ? 1.0f : 0.0f) - Av;
            a[16 + c] = (r == c ? 1.0f : 0.0f);
        }
#pragma unroll
        for (int col = 0; col < 16; ++col) {
            float v = (lane >= col && lane < 16) ? fabsf(a[col]) : -1.0f;
            int ix = lane;
#pragma unroll
            for (int o = 16; o > 0; o >>= 1) {
                float vo = __shfl_xor_sync(FULL, v, o);
                int   io = __shfl_xor_sync(FULL, ix, o);
                if (vo > v || (vo == v && io < ix)) { v = vo; ix = io; }
            }
            const int piv = ix;
            const int partner = (lane == col) ? piv : (lane == piv) ? col : lane;
#pragma unroll
            for (int k = 0; k < 32; ++k)
                a[k] = __shfl_sync(FULL, a[k], partner);
            const float pv  = __shfl_sync(FULL, a[col], col);
            const float inv = 1.0f / pv;
            const float fac = (lane == col) ? 0.0f : a[col];
#pragma unroll
            for (int k = 0; k < 32; ++k) {
                const float prs = __shfl_sync(FULL, a[k], col) * inv;
                a[k] = (lane == col) ? prs : fmaf(-fac, prs, a[k]);
            }
        }
        if (r < 16) {
#pragma unroll
            for (int c = 0; c < 16; ++c)
                g_M[r * 16 + c] = a[16 + c];
        }
    } else {
        const int d = warp;
        const float* pd = p + d * NP1;

        float wl[4];
#pragma unroll
        for (int q = 0; q < 4; ++q) {
            const int i = 4 * lane + q;
            wl[q] = (i < NP1) ? (expf(pd[i]) + 0.001f) : 0.0f;
        }
        const float w_next0 = __shfl_down_sync(FULL, wl[0], 1);

        float pre[4];
        float loc = 0.0f;
#pragma unroll
        for (int q = 0; q < 4; ++q) {
            const int i = 4 * lane + q;
            const float wip1 = (q < 3) ? wl[q + 1] : w_next0;
            const float v = (i < 99) ? (INT_LEN_F * wip1) : 0.0f;
            loc += v;
            pre[q] = loc;
        }
        float tot = loc;
#pragma unroll
        for (int o = 1; o < 32; o <<= 1) {
            const float t = __shfl_up_sync(FULL, tot, o);
            if (lane >= o) tot += t;
        }
        const float excl = tot - loc;
        float S[4];
#pragma unroll
        for (int q = 0; q < 4; ++q)
            S[q] = excl + (q == 0 ? 0.0f : pre[q - 1]);
        const float S_prevlast = __shfl_up_sync(FULL, S[3], 1);

        const float bd = b[d];
#pragma unroll
        for (int q = 0; q < 4; ++q) {
            const int idx = 4 * lane + q;
            if (idx < NP1) {
                const int   spi = idx > 0 ? idx - 1 : 0;
                const float Ssp = (idx == 0) ? 0.0f
                                : (q == 0)   ? S_prevlast
                                             : S[q - 1];
                const float w  = wl[q];
                const float sp = fmaf((float)spi, INT_LEN_F, VMIN_F);
                const float db = bd + Ssp;
                g_tab[d * NP1 + idx] = __floats2half2_rn(w, fmaf(-sp, w, db));
            }
        }
    }
}

// ---------------------------------------------------------------------------
// Main kernel: persistent grid-stride, 2 rows per thread per iteration.
// ---------------------------------------------------------------------------
__global__ void __launch_bounds__(256) scm_main_kernel(const float4* __restrict__ eps,
                                                       float4* __restrict__ out,
                                                       int B, int stride) {
    __shared__ __half2 s_tab[DIMS * NP1];
    for (int i = threadIdx.x; i < DIMS * NP1; i += 256) s_tab[i] = g_tab[i];
    __syncthreads();

    const int tid0 = blockIdx.x * 256 + threadIdx.x;

    for (int rowA = tid0; rowA < B; rowA += 2 * stride) {
        const int rowB = rowA + stride;
        const bool hasB = (rowB < B);

        // --- load both rows (8 independent LDG.128) ---
        const float4* epA = eps + (size_t)rowA * 4;
        const float4 a0 = __ldcs(epA + 0);
        const float4 a1 = __ldcs(epA + 1);
        const float4 a2 = __ldcs(epA + 2);
        const float4 a3 = __ldcs(epA + 3);

        const float4* epB = eps + (size_t)(hasB ? rowB : rowA) * 4;
        const float4 b0 = __ldcs(epB + 0);
        const float4 b1 = __ldcs(epB + 1);
        const float4 b2 = __ldcs(epB + 2);
        const float4 b3 = __ldcs(epB + 3);

        const float eA[16] = {a0.x, a0.y, a0.z, a0.w, a1.x, a1.y, a1.z, a1.w,
                              a2.x, a2.y, a2.z, a2.w, a3.x, a3.y, a3.z, a3.w};
        const float eB[16] = {b0.x, b0.y, b0.z, b0.w, b1.x, b1.y, b1.z, b1.w,
                              b2.x, b2.y, b2.z, b2.w, b3.x, b3.y, b3.z, b3.w};

        unsigned long long zA[8], zB[8];
#pragma unroll
        for (int j = 0; j < 8; ++j) { zA[j] = 0ULL; zB[j] = 0ULL; }

        // one constant-word stream serves BOTH rows
#pragma unroll
        for (int k = 0; k < 16; ++k) {
            const unsigned long long ekA = pack2(eA[k]);
            const unsigned long long ekB = pack2(eB[k]);
#pragma unroll
            for (int j = 0; j < 8; ++j) {
                const unsigned long long m = c_M2[k * 8 + j];
                zA[j] = ffma2(ekA, m, zA[j]);
                zB[j] = ffma2(ekB, m, zB[j]);
            }
        }

        // --- epilogue row A ---
        {
            float zv[16];
#pragma unroll
            for (int j2 = 0; j2 < 8; ++j2)
                unpack2(zA[j2], zv[2 * j2], zv[2 * j2 + 1]);
            int ti[16];
#pragma unroll
            for (int j = 0; j < 16; ++j) {
                int t = __float2int_rd(fmaf(zv[j], INV_INT_LEN_F, 49.5f));
                t = min(t, 99);
                t = max(t + 1, 0);
                ti[j] = j * NP1 + t;
            }
            __half2 u[16];
#pragma unroll
            for (int j = 0; j < 16; ++j) u[j] = s_tab[ti[j]];
            float o[16];
#pragma unroll
            for (int j = 0; j < 16; ++j) {
                const float2 wc = __half22float2(u[j]);
                o[j] = fmaf(zv[j], wc.x, wc.y);
            }
            float4* op = out + (size_t)rowA * 4;
            __stcs(op + 0, make_float4(o[0],  o[1],  o[2],  o[3]));
            __stcs(op + 1, make_float4(o[4],  o[5],  o[6],  o[7]));
            __stcs(op + 2, make_float4(o[8],  o[9],  o[10], o[11]));
            __stcs(op + 3, make_float4(o[12], o[13], o[14], o[15]));
        }

        // --- epilogue row B ---
        if (hasB) {
            float zv[16];
#pragma unroll
            for (int j2 = 0; j2 < 8; ++j2)
                unpack2(zB[j2], zv[2 * j2], zv[2 * j2 + 1]);
            int ti[16];
#pragma unroll
            for (int j = 0; j < 16; ++j) {
                int t = __float2int_rd(fmaf(zv[j], INV_INT_LEN_F, 49.5f));
                t = min(t, 99);
                t = max(t + 1, 0);
                ti[j] = j * NP1 + t;
            }
            __half2 u[16];
#pragma unroll
            for (int j = 0; j < 16; ++j) u[j] = s_tab[ti[j]];
            float o[16];
#pragma unroll
            for (int j = 0; j < 16; ++j) {
                const float2 wc = __half22float2(u[j]);
                o[j] = fmaf(zv[j], wc.x, wc.y);
            }
            float4* op = out + (size_t)rowB * 4;
            __stcs(op + 0, make_float4(o[0],  o[1],  o[2],  o[3]));
            __stcs(op + 1, make_float4(o[4],  o[5],  o[6],  o[7]));
            __stcs(op + 2, make_float4(o[8],  o[9],  o[10], o[11]));
            __stcs(op + 3, make_float4(o[12], o[13], o[14], o[15]));
        }
    }
}

// ---------------------------------------------------------------------------
extern "C" void kernel_launch(void* const* d_in, const int* in_sizes, int n_in,
                              void* d_out, int out_size) {
    const float* eps = nullptr;
    const float* A   = nullptr;
    const float* p   = nullptr;
    const float* b   = nullptr;
    int eps_elems = 0;
    for (int i = 0; i < n_in; ++i) {
        const int sz = in_sizes[i];
        if (sz == 256)       A = (const float*)d_in[i];
        else if (sz == 1616) p = (const float*)d_in[i];
        else if (sz == 16)   b = (const float*)d_in[i];
        else { eps = (const float*)d_in[i]; eps_elems = sz; }
    }
    const int B = eps_elems / 16;

    prep_kernel<<<1, 544>>>(A, p, b);

    void* gM_ptr = nullptr;
    cudaGetSymbolAddress(&gM_ptr, g_M);
    cudaMemcpyToSymbolAsync(c_M2, gM_ptr, DIMS * DIMS * sizeof(float), 0,
                            cudaMemcpyDeviceToDevice);

    int sm_count = 148;
    cudaDeviceGetAttribute(&sm_count, cudaDevAttrMultiProcessorCount, 0);
    int blocks_per_sm = 4;
    cudaOccupancyMaxActiveBlocksPerMultiprocessor(&blocks_per_sm, scm_main_kernel,
                                                  256, DIMS * NP1 * sizeof(__half2));
    if (blocks_per_sm < 1) blocks_per_sm = 1;
    const int blocks = sm_count * blocks_per_sm;
    const int stride = blocks * 256;
    scm_main_kernel<<<blocks, 256>>>((const float4*)eps, (float4*)d_out, B, stride);
}

// round 12
// speedup vs baseline: 1.0589x; 1.0589x over previous
#include <cuda_runtime.h>
#include <cuda_bf16.h>
#include <cuda_fp16.h>
#include <math.h>

// ---------------------------------------------------------------------------
// SCM: out = PWL( eps @ inv(I - A) )
//   eps: [B,16] f32, A: [16,16] f32, p: [16,101] f32, b: [16] f32
// Table per (dim, idx): half2{w, c}, c = delta_bias[spi] - sp*w -> out=fma(z,w,c)
// GEMV: packed fp32x2 FMA (FFMA2) vs 64-bit constant words.
// Index path is all-float (magic-number round): no F2I CVTs.
// ---------------------------------------------------------------------------

#define NP1 101
#define DIMS 16
#define VMIN_F (-5.0f)
#define INT_LEN_F (10.0f / 99.0f)
#define INV_INT_LEN_F (99.0f / 10.0f)
#define MAGIC_F 12582912.0f   // 1.5 * 2^23

__device__ float    g_M[DIMS * DIMS];
__device__ __half2  g_tab[DIMS * NP1];
__constant__ unsigned long long c_M2[DIMS * 8];

__device__ __forceinline__ unsigned long long ffma2(unsigned long long a,
                                                    unsigned long long b,
                                                    unsigned long long c) {
    unsigned long long d;
    asm("fma.rn.f32x2 %0, %1, %2, %3;" : "=l"(d) : "l"(a), "l"(b), "l"(c));
    return d;
}
__device__ __forceinline__ unsigned long long pack2(float x) {
    unsigned long long d;
    asm("mov.b64 %0, {%1, %1};" : "=l"(d) : "f"(x));
    return d;
}
__device__ __forceinline__ void unpack2(unsigned long long v, float& lo, float& hi) {
    asm("mov.b64 {%0, %1}, %2;" : "=f"(lo), "=f"(hi) : "l"(v));
}

// ---------------------------------------------------------------------------
// Prep: 1 block, 544 threads (17 warps), NO barriers.
// ---------------------------------------------------------------------------
__global__ void __launch_bounds__(544) prep_kernel(const float* __restrict__ A,
                                                   const float* __restrict__ p,
                                                   const float* __restrict__ b) {
    const int warp = threadIdx.x >> 5;
    const int lane = threadIdx.x & 31;
    const unsigned FULL = 0xffffffffu;

    if (warp == 16) {
        float a[32];
        const int r = lane;
#pragma unroll
        for (int c = 0; c < 16; ++c) {
            float Av = (r < 16) ? A[r * 16 + c] : 0.0f;
            a[c]      = (r == c ? 1.0f : 0.0f) - Av;
            a[16 + c] = (r == c ? 1.0f : 0.0f);
        }
#pragma unroll
        for (int col = 0; col < 16; ++col) {
            float v = (lane >= col && lane < 16) ? fabsf(a[col]) : -1.0f;
            int ix = lane;
#pragma unroll
            for (int o = 16; o > 0; o >>= 1) {
                float vo = __shfl_xor_sync(FULL, v, o);
                int   io = __shfl_xor_sync(FULL, ix, o);
                if (vo > v || (vo == v && io < ix)) { v = vo; ix = io; }
            }
            const int piv = ix;
            const int partner = (lane == col) ? piv : (lane == piv) ? col : lane;
#pragma unroll
            for (int k = 0; k < 32; ++k)
                a[k] = __shfl_sync(FULL, a[k], partner);
            const float pv  = __shfl_sync(FULL, a[col], col);
            const float inv = 1.0f / pv;
            const float fac = (lane == col) ? 0.0f : a[col];
#pragma unroll
            for (int k = 0; k < 32; ++k) {
                const float prs = __shfl_sync(FULL, a[k], col) * inv;
                a[k] = (lane == col) ? prs : fmaf(-fac, prs, a[k]);
            }
        }
        if (r < 16) {
#pragma unroll
            for (int c = 0; c < 16; ++c)
                g_M[r * 16 + c] = a[16 + c];
        }
    } else {
        const int d = warp;
        const float* pd = p + d * NP1;

        float wl[4];
#pragma unroll
        for (int q = 0; q < 4; ++q) {
            const int i = 4 * lane + q;
            wl[q] = (i < NP1) ? (expf(pd[i]) + 0.001f) : 0.0f;
        }
        const float w_next0 = __shfl_down_sync(FULL, wl[0], 1);

        float pre[4];
        float loc = 0.0f;
#pragma unroll
        for (int q = 0; q < 4; ++q) {
            const int i = 4 * lane + q;
            const float wip1 = (q < 3) ? wl[q + 1] : w_next0;
            const float v = (i < 99) ? (INT_LEN_F * wip1) : 0.0f;
            loc += v;
            pre[q] = loc;
        }
        float tot = loc;
#pragma unroll
        for (int o = 1; o < 32; o <<= 1) {
            const float t = __shfl_up_sync(FULL, tot, o);
            if (lane >= o) tot += t;
        }
        const float excl = tot - loc;
        float S[4];
#pragma unroll
        for (int q = 0; q < 4; ++q)
            S[q] = excl + (q == 0 ? 0.0f : pre[q - 1]);
        const float S_prevlast = __shfl_up_sync(FULL, S[3], 1);

        const float bd = b[d];
#pragma unroll
        for (int q = 0; q < 4; ++q) {
            const int idx = 4 * lane + q;
            if (idx < NP1) {
                const int   spi = idx > 0 ? idx - 1 : 0;
                const float Ssp = (idx == 0) ? 0.0f
                                : (q == 0)   ? S_prevlast
                                             : S[q - 1];
                const float w  = wl[q];
                const float sp = fmaf((float)spi, INT_LEN_F, VMIN_F);
                const float db = bd + Ssp;
                g_tab[d * NP1 + idx] = __floats2half2_rn(w, fmaf(-sp, w, db));
            }
        }
    }
}

// ---------------------------------------------------------------------------
// Epilogue for 8 dims [j0, j0+8): all-float index, batched gathers.
//   ti = round(clamp(zv*INV + 49.5 + 0.5 + 101j, 101j-0.499, 101j+99.501))
//   (round via +1.5*2^23, low mantissa bits = table offset incl. j*101)
// ---------------------------------------------------------------------------
template<int J0>
__device__ __forceinline__ void pwl_batch8(const unsigned long long* z2,
                                           const __half2* s_tab, float* o) {
    float zv[8];
#pragma unroll
    for (int q = 0; q < 4; ++q)
        unpack2(z2[J0 / 2 + q], zv[2 * q], zv[2 * q + 1]);

    int ti[8];
#pragma unroll
    for (int q = 0; q < 8; ++q) {
        const int j = J0 + q;
        const float base = 101.0f * (float)j;
        float y = fmaf(zv[q], INV_INT_LEN_F, 50.0f + base);  // u - 0.5 + 101j
        y = fminf(y, base + 99.501f);
        y = fmaxf(y, base - 0.499f);
        const float m = y + MAGIC_F;
        ti[q] = __float_as_int(m) & 0x3FFFFF;
    }
    __half2 u[8];
#pragma unroll
    for (int q = 0; q < 8; ++q) u[q] = s_tab[ti[q]];
#pragma unroll
    for (int q = 0; q < 8; ++q) {
        const float2 wc = __half22float2(u[q]);
        o[J0 + q] = fmaf(zv[q], wc.x, wc.y);
    }
}

// ---------------------------------------------------------------------------
// Main kernel: persistent grid-stride, 1 row/thread/iter.
// ---------------------------------------------------------------------------
__global__ void __launch_bounds__(256, 7) scm_main_kernel(const float4* __restrict__ eps,
                                                          float4* __restrict__ out,
                                                          int B, int stride) {
    __shared__ __half2 s_tab[DIMS * NP1];
    for (int i = threadIdx.x; i < DIMS * NP1; i += 256) s_tab[i] = g_tab[i];
    __syncthreads();

    for (int row = blockIdx.x * 256 + threadIdx.x; row < B; row += stride) {
        const float4* ep = eps + (size_t)row * 4;
        const float4 e0 = __ldcs(ep + 0);
        const float4 e1 = __ldcs(ep + 1);
        const float4 e2 = __ldcs(ep + 2);
        const float4 e3 = __ldcs(ep + 3);

        const float e[16] = {e0.x, e0.y, e0.z, e0.w,
                             e1.x, e1.y, e1.z, e1.w,
                             e2.x, e2.y, e2.z, e2.w,
                             e3.x, e3.y, e3.z, e3.w};

        unsigned long long z2[8];
#pragma unroll
        for (int j = 0; j < 8; ++j) z2[j] = 0ULL;

#pragma unroll
        for (int k = 0; k < 16; ++k) {
            const unsigned long long ek2 = pack2(e[k]);
#pragma unroll
            for (int j = 0; j < 8; ++j)
                z2[j] = ffma2(ek2, c_M2[k * 8 + j], z2[j]);
        }

        float o[16];
        pwl_batch8<0>(z2, s_tab, o);
        pwl_batch8<8>(z2, s_tab, o);

        float4* op = out + (size_t)row * 4;
        __stcs(op + 0, make_float4(o[0],  o[1],  o[2],  o[3]));
        __stcs(op + 1, make_float4(o[4],  o[5],  o[6],  o[7]));
        __stcs(op + 2, make_float4(o[8],  o[9],  o[10], o[11]));
        __stcs(op + 3, make_float4(o[12], o[13], o[14], o[15]));
    }
}

// ---------------------------------------------------------------------------
extern "C" void kernel_launch(void* const* d_in, const int* in_sizes, int n_in,
                              void* d_out, int out_size) {
    const float* eps = nullptr;
    const float* A   = nullptr;
    const float* p   = nullptr;
    const float* b   = nullptr;
    int eps_elems = 0;
    for (int i = 0; i < n_in; ++i) {
        const int sz = in_sizes[i];
        if (sz == 256)       A = (const float*)d_in[i];
        else if (sz == 1616) p = (const float*)d_in[i];
        else if (sz == 16)   b = (const float*)d_in[i];
        else { eps = (const float*)d_in[i]; eps_elems = sz; }
    }
    const int B = eps_elems / 16;

    prep_kernel<<<1, 544>>>(A, p, b);

    void* gM_ptr = nullptr;
    cudaGetSymbolAddress(&gM_ptr, g_M);
    cudaMemcpyToSymbolAsync(c_M2, gM_ptr, DIMS * DIMS * sizeof(float), 0,
                            cudaMemcpyDeviceToDevice);

    int sm_count = 148;
    cudaDeviceGetAttribute(&sm_count, cudaDevAttrMultiProcessorCount, 0);
    int blocks_per_sm = 7;
    cudaOccupancyMaxActiveBlocksPerMultiprocessor(&blocks_per_sm, scm_main_kernel,
                                                  256, DIMS * NP1 * sizeof(__half2));
    if (blocks_per_sm < 1) blocks_per_sm = 1;
    const int blocks = sm_count * blocks_per_sm;
    const int stride = blocks * 256;
    scm_main_kernel<<<blocks, 256>>>((const float4*)eps, (float4*)d_out, B, stride);
}

// round 13
// speedup vs baseline: 1.1433x; 1.0798x over previous
#include <cuda_runtime.h>
#include <cuda_bf16.h>
#include <cuda_fp16.h>
#include <math.h>

// ---------------------------------------------------------------------------
// SCM: out = PWL( eps @ inv(I - A) )
//   eps: [B,16] f32, A: [16,16] f32, p: [16,101] f32, b: [16] f32
// Table per (dim, idx): half2{w, c}, c = delta_bias[spi] - sp*w -> out=fma(z,w,c)
// GEMV: packed fp32x2 FMA (FFMA2) vs 64-bit constant words.
// Global I/O: 256-bit vector loads/stores (sm_100+ v8.f32).
// ---------------------------------------------------------------------------

#define NP1 101
#define DIMS 16
#define VMIN_F (-5.0f)
#define INT_LEN_F (10.0f / 99.0f)
#define INV_INT_LEN_F (99.0f / 10.0f)
#define MAGIC_F 12582912.0f   // 1.5 * 2^23

__device__ float    g_M[DIMS * DIMS];
__device__ __half2  g_tab[DIMS * NP1];
__constant__ unsigned long long c_M2[DIMS * 8];

__device__ __forceinline__ unsigned long long ffma2(unsigned long long a,
                                                    unsigned long long b,
                                                    unsigned long long c) {
    unsigned long long d;
    asm("fma.rn.f32x2 %0, %1, %2, %3;" : "=l"(d) : "l"(a), "l"(b), "l"(c));
    return d;
}
__device__ __forceinline__ unsigned long long pack2(float x) {
    unsigned long long d;
    asm("mov.b64 %0, {%1, %1};" : "=l"(d) : "f"(x));
    return d;
}
__device__ __forceinline__ void unpack2(unsigned long long v, float& lo, float& hi) {
    asm("mov.b64 {%0, %1}, %2;" : "=f"(lo), "=f"(hi) : "l"(v));
}

__device__ __forceinline__ void ldg256(const float* ptr, float* v) {
    asm("ld.global.cs.v8.f32 {%0,%1,%2,%3,%4,%5,%6,%7}, [%8];"
        : "=f"(v[0]), "=f"(v[1]), "=f"(v[2]), "=f"(v[3]),
          "=f"(v[4]), "=f"(v[5]), "=f"(v[6]), "=f"(v[7])
        : "l"(ptr));
}
__device__ __forceinline__ void stg256(float* ptr, const float* v) {
    asm volatile("st.global.cs.v8.f32 [%0], {%1,%2,%3,%4,%5,%6,%7,%8};"
        :: "l"(ptr),
           "f"(v[0]), "f"(v[1]), "f"(v[2]), "f"(v[3]),
           "f"(v[4]), "f"(v[5]), "f"(v[6]), "f"(v[7])
        : "memory");
}

// ---------------------------------------------------------------------------
// Prep: 1 block, 544 threads (17 warps), NO barriers.
// ---------------------------------------------------------------------------
__global__ void __launch_bounds__(544) prep_kernel(const float* __restrict__ A,
                                                   const float* __restrict__ p,
                                                   const float* __restrict__ b) {
    const int warp = threadIdx.x >> 5;
    const int lane = threadIdx.x & 31;
    const unsigned FULL = 0xffffffffu;

    if (warp == 16) {
        float a[32];
        const int r = lane;
#pragma unroll
        for (int c = 0; c < 16; ++c) {
            float Av = (r < 16) ? A[r * 16 + c] : 0.0f;
            a[c]      = (r == c ? 1.0f : 0.0f) - Av;
            a[16 + c] = (r == c ? 1.0f : 0.0f);
        }
#pragma unroll
        for (int col = 0; col < 16; ++col) {
            float v = (lane >= col && lane < 16) ? fabsf(a[col]) : -1.0f;
            int ix = lane;
#pragma unroll
            for (int o = 16; o > 0; o >>= 1) {
                float vo = __shfl_xor_sync(FULL, v, o);
                int   io = __shfl_xor_sync(FULL, ix, o);
                if (vo > v || (vo == v && io < ix)) { v = vo; ix = io; }
            }
            const int piv = ix;
            const int partner = (lane == col) ? piv : (lane == piv) ? col : lane;
#pragma unroll
            for (int k = 0; k < 32; ++k)
                a[k] = __shfl_sync(FULL, a[k], partner);
            const float pv  = __shfl_sync(FULL, a[col], col);
            const float inv = 1.0f / pv;
            const float fac = (lane == col) ? 0.0f : a[col];
#pragma unroll
            for (int k = 0; k < 32; ++k) {
                const float prs = __shfl_sync(FULL, a[k], col) * inv;
                a[k] = (lane == col) ? prs : fmaf(-fac, prs, a[k]);
            }
        }
        if (r < 16) {
#pragma unroll
            for (int c = 0; c < 16; ++c)
                g_M[r * 16 + c] = a[16 + c];
        }
    } else {
        const int d = warp;
        const float* pd = p + d * NP1;

        float wl[4];
#pragma unroll
        for (int q = 0; q < 4; ++q) {
            const int i = 4 * lane + q;
            wl[q] = (i < NP1) ? (expf(pd[i]) + 0.001f) : 0.0f;
        }
        const float w_next0 = __shfl_down_sync(FULL, wl[0], 1);

        float pre[4];
        float loc = 0.0f;
#pragma unroll
        for (int q = 0; q < 4; ++q) {
            const int i = 4 * lane + q;
            const float wip1 = (q < 3) ? wl[q + 1] : w_next0;
            const float v = (i < 99) ? (INT_LEN_F * wip1) : 0.0f;
            loc += v;
            pre[q] = loc;
        }
        float tot = loc;
#pragma unroll
        for (int o = 1; o < 32; o <<= 1) {
            const float t = __shfl_up_sync(FULL, tot, o);
            if (lane >= o) tot += t;
        }
        const float excl = tot - loc;
        float S[4];
#pragma unroll
        for (int q = 0; q < 4; ++q)
            S[q] = excl + (q == 0 ? 0.0f : pre[q - 1]);
        const float S_prevlast = __shfl_up_sync(FULL, S[3], 1);

        const float bd = b[d];
#pragma unroll
        for (int q = 0; q < 4; ++q) {
            const int idx = 4 * lane + q;
            if (idx < NP1) {
                const int   spi = idx > 0 ? idx - 1 : 0;
                const float Ssp = (idx == 0) ? 0.0f
                                : (q == 0)   ? S_prevlast
                                             : S[q - 1];
                const float w  = wl[q];
                const float sp = fmaf((float)spi, INT_LEN_F, VMIN_F);
                const float db = bd + Ssp;
                g_tab[d * NP1 + idx] = __floats2half2_rn(w, fmaf(-sp, w, db));
            }
        }
    }
}

// ---------------------------------------------------------------------------
// Epilogue for 8 dims [J0, J0+8): all-float index, batched gathers.
// ---------------------------------------------------------------------------
template<int J0>
__device__ __forceinline__ void pwl_batch8(const unsigned long long* z2,
                                           const __half2* s_tab, float* o) {
    float zv[8];
#pragma unroll
    for (int q = 0; q < 4; ++q)
        unpack2(z2[J0 / 2 + q], zv[2 * q], zv[2 * q + 1]);

    int ti[8];
#pragma unroll
    for (int q = 0; q < 8; ++q) {
        const int j = J0 + q;
        const float base = 101.0f * (float)j;
        float y = fmaf(zv[q], INV_INT_LEN_F, 50.0f + base);
        y = fminf(y, base + 99.501f);
        y = fmaxf(y, base - 0.499f);
        const float m = y + MAGIC_F;
        ti[q] = __float_as_int(m) & 0x3FFFFF;
    }
    __half2 u[8];
#pragma unroll
    for (int q = 0; q < 8; ++q) u[q] = s_tab[ti[q]];
#pragma unroll
    for (int q = 0; q < 8; ++q) {
        const float2 wc = __half22float2(u[q]);
        o[J0 + q] = fmaf(zv[q], wc.x, wc.y);
    }
}

// ---------------------------------------------------------------------------
// Main kernel: persistent grid-stride, 1 row/thread/iter, 256-bit global I/O.
// ---------------------------------------------------------------------------
__global__ void __launch_bounds__(256) scm_main_kernel(const float* __restrict__ eps,
                                                       float* __restrict__ out,
                                                       int B, int stride) {
    __shared__ __half2 s_tab[DIMS * NP1];
    for (int i = threadIdx.x; i < DIMS * NP1; i += 256) s_tab[i] = g_tab[i];
    __syncthreads();

    for (int row = blockIdx.x * 256 + threadIdx.x; row < B; row += stride) {
        const float* ep = eps + (size_t)row * 16;
        float e[16];
        ldg256(ep, e);
        ldg256(ep + 8, e + 8);

        unsigned long long z2[8];
#pragma unroll
        for (int j = 0; j < 8; ++j) z2[j] = 0ULL;

#pragma unroll
        for (int k = 0; k < 16; ++k) {
            const unsigned long long ek2 = pack2(e[k]);
#pragma unroll
            for (int j = 0; j < 8; ++j)
                z2[j] = ffma2(ek2, c_M2[k * 8 + j], z2[j]);
        }

        float o[16];
        pwl_batch8<0>(z2, s_tab, o);
        pwl_batch8<8>(z2, s_tab, o);

        float* op = out + (size_t)row * 16;
        stg256(op, o);
        stg256(op + 8, o + 8);
    }
}

// ---------------------------------------------------------------------------
extern "C" void kernel_launch(void* const* d_in, const int* in_sizes, int n_in,
                              void* d_out, int out_size) {
    const float* eps = nullptr;
    const float* A   = nullptr;
    const float* p   = nullptr;
    const float* b   = nullptr;
    int eps_elems = 0;
    for (int i = 0; i < n_in; ++i) {
        const int sz = in_sizes[i];
        if (sz == 256)       A = (const float*)d_in[i];
        else if (sz == 1616) p = (const float*)d_in[i];
        else if (sz == 16)   b = (const float*)d_in[i];
        else { eps = (const float*)d_in[i]; eps_elems = sz; }
    }
    const int B = eps_elems / 16;

    prep_kernel<<<1, 544>>>(A, p, b);

    void* gM_ptr = nullptr;
    cudaGetSymbolAddress(&gM_ptr, g_M);
    cudaMemcpyToSymbolAsync(c_M2, gM_ptr, DIMS * DIMS * sizeof(float), 0,
                            cudaMemcpyDeviceToDevice);

    int sm_count = 148;
    cudaDeviceGetAttribute(&sm_count, cudaDevAttrMultiProcessorCount, 0);
    int blocks_per_sm = 8;
    cudaOccupancyMaxActiveBlocksPerMultiprocessor(&blocks_per_sm, scm_main_kernel,
                                                  256, DIMS * NP1 * sizeof(__half2));
    if (blocks_per_sm < 1) blocks_per_sm = 1;
    const int blocks = sm_count * blocks_per_sm;
    const int stride = blocks * 256;
    scm_main_kernel<<<blocks, 256>>>((const float*)eps, (float*)d_out, B, stride);
}

// round 14
// speedup vs baseline: 1.1582x; 1.0130x over previous
#include <cuda_runtime.h>
#include <cuda_bf16.h>
#include <cuda_fp16.h>
#include <math.h>

// ---------------------------------------------------------------------------
// SCM: out = PWL( eps @ inv(I - A) )
//   eps: [B,16] f32, A: [16,16] f32, p: [16,101] f32, b: [16] f32
// Table per (dim, idx): half2{w, c}, c = delta_bias[spi] - sp*w -> out=fma(z,w,c)
// GEMV: packed fp32x2 FMA (FFMA2) vs 64-bit constant words.
// Global I/O: 256-bit vector loads/stores (sm_100+ v8.f32), next-row prefetch.
// ---------------------------------------------------------------------------

#define NP1 101
#define DIMS 16
#define VMIN_F (-5.0f)
#define INT_LEN_F (10.0f / 99.0f)
#define INV_INT_LEN_F (99.0f / 10.0f)
#define MAGIC_F 12582912.0f   // 1.5 * 2^23

__device__ float    g_M[DIMS * DIMS];
__device__ __half2  g_tab[DIMS * NP1];
__constant__ unsigned long long c_M2[DIMS * 8];

__device__ __forceinline__ unsigned long long ffma2(unsigned long long a,
                                                    unsigned long long b,
                                                    unsigned long long c) {
    unsigned long long d;
    asm("fma.rn.f32x2 %0, %1, %2, %3;" : "=l"(d) : "l"(a), "l"(b), "l"(c));
    return d;
}
__device__ __forceinline__ unsigned long long pack2(float x) {
    unsigned long long d;
    asm("mov.b64 %0, {%1, %1};" : "=l"(d) : "f"(x));
    return d;
}
__device__ __forceinline__ void unpack2(unsigned long long v, float& lo, float& hi) {
    asm("mov.b64 {%0, %1}, %2;" : "=f"(lo), "=f"(hi) : "l"(v));
}

__device__ __forceinline__ void ldg256(const float* ptr, float* v) {
    asm("ld.global.cs.v8.f32 {%0,%1,%2,%3,%4,%5,%6,%7}, [%8];"
        : "=f"(v[0]), "=f"(v[1]), "=f"(v[2]), "=f"(v[3]),
          "=f"(v[4]), "=f"(v[5]), "=f"(v[6]), "=f"(v[7])
        : "l"(ptr));
}
__device__ __forceinline__ void stg256(float* ptr, const float* v) {
    asm volatile("st.global.cs.v8.f32 [%0], {%1,%2,%3,%4,%5,%6,%7,%8};"
        :: "l"(ptr),
           "f"(v[0]), "f"(v[1]), "f"(v[2]), "f"(v[3]),
           "f"(v[4]), "f"(v[5]), "f"(v[6]), "f"(v[7])
        : "memory");
}

// ---------------------------------------------------------------------------
// Prep: 1 block, 544 threads (17 warps), NO barriers.
// ---------------------------------------------------------------------------
__global__ void __launch_bounds__(544) prep_kernel(const float* __restrict__ A,
                                                   const float* __restrict__ p,
                                                   const float* __restrict__ b) {
    const int warp = threadIdx.x >> 5;
    const int lane = threadIdx.x & 31;
    const unsigned FULL = 0xffffffffu;

    if (warp == 16) {
        float a[32];
        const int r = lane;
#pragma unroll
        for (int c = 0; c < 16; ++c) {
            float Av = (r < 16) ? A[r * 16 + c] : 0.0f;
            a[c]      = (r == c ? 1.0f : 0.0f) - Av;
            a[16 + c] = (r == c ? 1.0f : 0.0f);
        }
#pragma unroll
        for (int col = 0; col < 16; ++col) {
            float v = (lane >= col && lane < 16) ? fabsf(a[col]) : -1.0f;
            int ix = lane;
#pragma unroll
            for (int o = 16; o > 0; o >>= 1) {
                float vo = __shfl_xor_sync(FULL, v, o);
                int   io = __shfl_xor_sync(FULL, ix, o);
                if (vo > v || (vo == v && io < ix)) { v = vo; ix = io; }
            }
            const int piv = ix;
            const int partner = (lane == col) ? piv : (lane == piv) ? col : lane;
#pragma unroll
            for (int k = 0; k < 32; ++k)
                a[k] = __shfl_sync(FULL, a[k], partner);
            const float pv  = __shfl_sync(FULL, a[col], col);
            const float inv = 1.0f / pv;
            const float fac = (lane == col) ? 0.0f : a[col];
#pragma unroll
            for (int k = 0; k < 32; ++k) {
                const float prs = __shfl_sync(FULL, a[k], col) * inv;
                a[k] = (lane == col) ? prs : fmaf(-fac, prs, a[k]);
            }
        }
        if (r < 16) {
#pragma unroll
            for (int c = 0; c < 16; ++c)
                g_M[r * 16 + c] = a[16 + c];
        }
    } else {
        const int d = warp;
        const float* pd = p + d * NP1;

        float wl[4];
#pragma unroll
        for (int q = 0; q < 4; ++q) {
            const int i = 4 * lane + q;
            wl[q] = (i < NP1) ? (expf(pd[i]) + 0.001f) : 0.0f;
        }
        const float w_next0 = __shfl_down_sync(FULL, wl[0], 1);

        float pre[4];
        float loc = 0.0f;
#pragma unroll
        for (int q = 0; q < 4; ++q) {
            const int i = 4 * lane + q;
            const float wip1 = (q < 3) ? wl[q + 1] : w_next0;
            const float v = (i < 99) ? (INT_LEN_F * wip1) : 0.0f;
            loc += v;
            pre[q] = loc;
        }
        float tot = loc;
#pragma unroll
        for (int o = 1; o < 32; o <<= 1) {
            const float t = __shfl_up_sync(FULL, tot, o);
            if (lane >= o) tot += t;
        }
        const float excl = tot - loc;
        float S[4];
#pragma unroll
        for (int q = 0; q < 4; ++q)
            S[q] = excl + (q == 0 ? 0.0f : pre[q - 1]);
        const float S_prevlast = __shfl_up_sync(FULL, S[3], 1);

        const float bd = b[d];
#pragma unroll
        for (int q = 0; q < 4; ++q) {
            const int idx = 4 * lane + q;
            if (idx < NP1) {
                const int   spi = idx > 0 ? idx - 1 : 0;
                const float Ssp = (idx == 0) ? 0.0f
                                : (q == 0)   ? S_prevlast
                                             : S[q - 1];
                const float w  = wl[q];
                const float sp = fmaf((float)spi, INT_LEN_F, VMIN_F);
                const float db = bd + Ssp;
                g_tab[d * NP1 + idx] = __floats2half2_rn(w, fmaf(-sp, w, db));
            }
        }
    }
}

// ---------------------------------------------------------------------------
// Epilogue for 8 dims [J0, J0+8): all-float index, batched gathers.
// ---------------------------------------------------------------------------
template<int J0>
__device__ __forceinline__ void pwl_batch8(const unsigned long long* z2,
                                           const __half2* s_tab, float* o) {
    float zv[8];
#pragma unroll
    for (int q = 0; q < 4; ++q)
        unpack2(z2[J0 / 2 + q], zv[2 * q], zv[2 * q + 1]);

    int ti[8];
#pragma unroll
    for (int q = 0; q < 8; ++q) {
        const int j = J0 + q;
        const float base = 101.0f * (float)j;
        float y = fmaf(zv[q], INV_INT_LEN_F, 50.0f + base);
        y = fminf(y, base + 99.501f);
        y = fmaxf(y, base - 0.499f);
        const float m = y + MAGIC_F;
        ti[q] = __float_as_int(m) & 0x3FFFFF;
    }
    __half2 u[8];
#pragma unroll
    for (int q = 0; q < 8; ++q) u[q] = s_tab[ti[q]];
#pragma unroll
    for (int q = 0; q < 8; ++q) {
        const float2 wc = __half22float2(u[q]);
        o[J0 + q] = fmaf(zv[q], wc.x, wc.y);
    }
}

// ---------------------------------------------------------------------------
// Main kernel: persistent grid-stride, 1 row/thread/iter, 256-bit I/O,
// next-row prefetch double-buffering.
// ---------------------------------------------------------------------------
__global__ void __launch_bounds__(256) scm_main_kernel(const float* __restrict__ eps,
                                                       float* __restrict__ out,
                                                       int B, int stride) {
    __shared__ __half2 s_tab[DIMS * NP1];
    for (int i = threadIdx.x; i < DIMS * NP1; i += 256) s_tab[i] = g_tab[i];
    __syncthreads();

    int row = blockIdx.x * 256 + threadIdx.x;
    if (row >= B) return;

    float e[16];
    {
        const float* ep = eps + (size_t)row * 16;
        ldg256(ep, e);
        ldg256(ep + 8, e + 8);
    }

    while (true) {
        const int next = row + stride;

        // prefetch next row before current compute
        float en[16];
        if (next < B) {
            const float* np = eps + (size_t)next * 16;
            ldg256(np, en);
            ldg256(np + 8, en + 8);
        }

        unsigned long long z2[8];
#pragma unroll
        for (int j = 0; j < 8; ++j) z2[j] = 0ULL;

#pragma unroll
        for (int k = 0; k < 16; ++k) {
            const unsigned long long ek2 = pack2(e[k]);
#pragma unroll
            for (int j = 0; j < 8; ++j)
                z2[j] = ffma2(ek2, c_M2[k * 8 + j], z2[j]);
        }

        float o[16];
        pwl_batch8<0>(z2, s_tab, o);
        pwl_batch8<8>(z2, s_tab, o);

        float* op = out + (size_t)row * 16;
        stg256(op, o);
        stg256(op + 8, o + 8);

        if (next >= B) break;
        row = next;
#pragma unroll
        for (int k = 0; k < 16; ++k) e[k] = en[k];
    }
}

// ---------------------------------------------------------------------------
extern "C" void kernel_launch(void* const* d_in, const int* in_sizes, int n_in,
                              void* d_out, int out_size) {
    const float* eps = nullptr;
    const float* A   = nullptr;
    const float* p   = nullptr;
    const float* b   = nullptr;
    int eps_elems = 0;
    for (int i = 0; i < n_in; ++i) {
        const int sz = in_sizes[i];
        if (sz == 256)       A = (const float*)d_in[i];
        else if (sz == 1616) p = (const float*)d_in[i];
        else if (sz == 16)   b = (const float*)d_in[i];
        else { eps = (const float*)d_in[i]; eps_elems = sz; }
    }
    const int B = eps_elems / 16;

    prep_kernel<<<1, 544>>>(A, p, b);

    void* gM_ptr = nullptr;
    cudaGetSymbolAddress(&gM_ptr, g_M);
    cudaMemcpyToSymbolAsync(c_M2, gM_ptr, DIMS * DIMS * sizeof(float), 0,
                            cudaMemcpyDeviceToDevice);

    int sm_count = 148;
    cudaDeviceGetAttribute(&sm_count, cudaDevAttrMultiProcessorCount, 0);
    int blocks_per_sm = 5;
    cudaOccupancyMaxActiveBlocksPerMultiprocessor(&blocks_per_sm, scm_main_kernel,
                                                  256, DIMS * NP1 * sizeof(__half2));
    if (blocks_per_sm < 1) blocks_per_sm = 1;
    const int blocks = sm_count * blocks_per_sm;
    const int stride = blocks * 256;
    scm_main_kernel<<<blocks, 256>>>((const float*)eps, (float*)d_out, B, stride);
}